// round 13
// baseline (speedup 1.0000x reference)
#include <cuda_runtime.h>

#define B_  4
#define S_  2048
#define D_  1024
#define H_  16
#define DK_ 64

// Head-major scratch: [b, h, s, dk]
__device__ float g_q[B_ * H_ * S_ * DK_];
__device__ float g_k[B_ * H_ * S_ * DK_];
__device__ float g_v[B_ * H_ * S_ * DK_];

// ---------------------------------------------------------------------------
// Fused QKV projection GEMM: C = X @ W? + b?   (X: [8192,1024], W: [1024,1024])
// BM=BN=128, BK=16, 256 threads, 8x8 per-thread tile.
// which = nb>>3 selects Wq/Wk/Wv. q additionally written to d_out (q_a).
// ---------------------------------------------------------------------------
#define BM  128
#define BN  128
#define BKK 16

__global__ __launch_bounds__(256) void qkv_gemm(
    const float* __restrict__ X,
    const float* __restrict__ Wq, const float* __restrict__ bq,
    const float* __restrict__ Wk, const float* __restrict__ bk,
    const float* __restrict__ Wv, const float* __restrict__ bv,
    float* __restrict__ qa_out)
{
    __shared__ float As[BKK][BM];   // transposed: As[k][m]
    __shared__ float Bs[BKK][BN];   // Bs[k][n]

    const int nb = blockIdx.x;          // 0..23
    const int mb = blockIdx.y;          // 0..63
    const int which = nb >> 3;          // 0=q 1=k 2=v
    const int n0 = (nb & 7) * BN;       // column offset within the 1024-wide weight
    const int m0 = mb * BM;

    const float* W;
    const float* bias;
    if (which == 0)      { W = Wq; bias = bq; }
    else if (which == 1) { W = Wk; bias = bk; }
    else                 { W = Wv; bias = bv; }

    const int tid = threadIdx.x;
    const int tx  = tid & 15;
    const int ty  = tid >> 4;

    float acc[8][8];
#pragma unroll
    for (int i = 0; i < 8; i++)
#pragma unroll
        for (int j = 0; j < 8; j++) acc[i][j] = 0.0f;

    for (int kt = 0; kt < D_ / BKK; kt++) {
        const int k0 = kt * BKK;

        // global -> regs (2 float4 of A, 2 float4 of B per thread)
        float4 af[2], bf[2];
#pragma unroll
        for (int u = 0; u < 2; u++) {
            int idx  = tid + u * 256;
            int row  = idx >> 2;        // 0..127
            int c4   = idx & 3;         // 0..3
            af[u] = *(const float4*)&X[(size_t)(m0 + row) * D_ + k0 + c4 * 4];
            int krow = idx >> 5;        // 0..15
            int bc4  = idx & 31;        // 0..31
            bf[u] = *(const float4*)&W[(size_t)(k0 + krow) * D_ + n0 + bc4 * 4];
        }

        __syncthreads();                // previous tile's compute done
#pragma unroll
        for (int u = 0; u < 2; u++) {
            int idx  = tid + u * 256;
            int row  = idx >> 2;
            int c4   = idx & 3;
            As[c4 * 4 + 0][row] = af[u].x;
            As[c4 * 4 + 1][row] = af[u].y;
            As[c4 * 4 + 2][row] = af[u].z;
            As[c4 * 4 + 3][row] = af[u].w;
            int krow = idx >> 5;
            int bc4  = idx & 31;
            *(float4*)&Bs[krow][bc4 * 4] = bf[u];
        }
        __syncthreads();

#pragma unroll
        for (int k = 0; k < BKK; k++) {
            float a[8], b8[8];
            *(float4*)&a[0]  = *(const float4*)&As[k][ty * 8];
            *(float4*)&a[4]  = *(const float4*)&As[k][ty * 8 + 4];
            *(float4*)&b8[0] = *(const float4*)&Bs[k][tx * 8];
            *(float4*)&b8[4] = *(const float4*)&Bs[k][tx * 8 + 4];
#pragma unroll
            for (int i = 0; i < 8; i++)
#pragma unroll
                for (int j = 0; j < 8; j++)
                    acc[i][j] += a[i] * b8[j];
        }
    }

    // epilogue: bias + route to head-major scratch (and q_a for the Q path)
#pragma unroll
    for (int i = 0; i < 8; i++) {
        const int r = m0 + ty * 8 + i;      // global row in [0, 8192)
        const int b = r >> 11;              // / 2048
        const int s = r & 2047;
#pragma unroll
        for (int j = 0; j < 8; j++) {
            const int c = n0 + tx * 8 + j;  // col within this weight's 1024
            const float v = acc[i][j] + bias[c];
            const int h  = c >> 6;
            const int dk = c & 63;
            const size_t hidx = (size_t)((b * H_ + h) * S_ + s) * DK_ + dk;
            if (which == 0) {
                qa_out[(size_t)r * D_ + c] = v;
                g_q[hidx] = v;
            } else if (which == 1) {
                g_k[hidx] = v;
            } else {
                g_v[hidx] = v;
            }
        }
    }
}

// ---------------------------------------------------------------------------
// Flash-style attention per (b,h) and 64-query tile. Key tiles of 64,
// loop bounded by length[b]. Faithful: e = exp(s/8)*mask, out = (P@V)/(sum+1e-8)
// 256 threads as 16x16, 4x4 micro-tiles. Dynamic smem ~70 KB.
// ---------------------------------------------------------------------------
#define LD 68   // padded leading dim (keeps float4 alignment, breaks conflicts)

__global__ __launch_bounds__(256) void attn_kernel(
    const int* __restrict__ length, float* __restrict__ ctx)
{
    extern __shared__ float sm[];
    float* Qs    = sm;               // [d][q] : Qs[d*LD + q]
    float* Ks    = sm + 64 * LD;     // [d][k]
    float* Vs    = sm + 2 * 64 * LD; // [k][d]
    float* Ps    = sm + 3 * 64 * LD; // [k][q]
    float* denom = sm + 4 * 64 * LD; // [64]

    const int bh = blockIdx.y;       // 0..63
    const int b  = bh >> 4;
    const int h  = bh & 15;
    const int qt = blockIdx.x;       // 0..31
    const int len = length[b];

    const int tid = threadIdx.x;
    const int tx  = tid & 15;
    const int ty  = tid >> 4;

    // Load Q tile transposed: Qs[d][q]
    const float* qbase = g_q + (size_t)(bh * S_ + qt * 64) * DK_;
#pragma unroll
    for (int it = 0; it < 16; it++) {
        int lin = it * 256 + tid;
        int s = lin >> 6, d = lin & 63;
        Qs[d * LD + s] = qbase[lin];
    }
    if (tid < 64) denom[tid] = 0.0f;

    float acc[4][4];
#pragma unroll
    for (int i = 0; i < 4; i++)
#pragma unroll
        for (int j = 0; j < 4; j++) acc[i][j] = 0.0f;

    const int nkt = (len + 63) >> 6;
    for (int kt = 0; kt < nkt; kt++) {
        __syncthreads();  // also guards Qs/denom init on kt==0, prev PV reads otherwise
        const float* kb = g_k + (size_t)(bh * S_ + kt * 64) * DK_;
        const float* vb = g_v + (size_t)(bh * S_ + kt * 64) * DK_;
#pragma unroll
        for (int it = 0; it < 16; it++) {
            int lin = it * 256 + tid;
            int r = lin >> 6, d = lin & 63;
            Ks[d * LD + r] = kb[lin];  // transposed
            Vs[r * LD + d] = vb[lin];  // natural
        }
        __syncthreads();

        // S tile: sc[i][j] = sum_d Q[q_i][d] * K[k_j][d]
        float sc[4][4];
#pragma unroll
        for (int i = 0; i < 4; i++)
#pragma unroll
            for (int j = 0; j < 4; j++) sc[i][j] = 0.0f;

#pragma unroll 16
        for (int d = 0; d < 64; d++) {
            float4 a  = *(const float4*)&Qs[d * LD + ty * 4];
            float4 kk = *(const float4*)&Ks[d * LD + tx * 4];
            sc[0][0] += a.x * kk.x; sc[0][1] += a.x * kk.y; sc[0][2] += a.x * kk.z; sc[0][3] += a.x * kk.w;
            sc[1][0] += a.y * kk.x; sc[1][1] += a.y * kk.y; sc[1][2] += a.y * kk.z; sc[1][3] += a.y * kk.w;
            sc[2][0] += a.z * kk.x; sc[2][1] += a.z * kk.y; sc[2][2] += a.z * kk.z; sc[2][3] += a.z * kk.w;
            sc[3][0] += a.w * kk.x; sc[3][1] += a.w * kk.y; sc[3][2] += a.w * kk.z; sc[3][3] += a.w * kk.w;
        }

        // exp + mask, store P transposed, partial row sums
        float rs[4] = {0.0f, 0.0f, 0.0f, 0.0f};
        const int kg0 = kt * 64 + tx * 4;
#pragma unroll
        for (int j = 0; j < 4; j++) {
            const float m = (kg0 + j < len) ? 1.0f : 0.0f;
#pragma unroll
            for (int i = 0; i < 4; i++) {
                float e = __expf(sc[i][j] * 0.125f) * m;
                Ps[(tx * 4 + j) * LD + ty * 4 + i] = e;
                rs[i] += e;
            }
        }
        // reduce over tx (low 4 lane bits)
#pragma unroll
        for (int off = 1; off < 16; off <<= 1) {
#pragma unroll
            for (int i = 0; i < 4; i++)
                rs[i] += __shfl_xor_sync(0xffffffffu, rs[i], off);
        }
        if (tx == 0) {
#pragma unroll
            for (int i = 0; i < 4; i++) denom[ty * 4 + i] += rs[i];
        }
        __syncthreads();

        // acc += P @ V : acc[i][j] over (q_i, d_j), contraction over keys
#pragma unroll 16
        for (int kk = 0; kk < 64; kk++) {
            float4 p = *(const float4*)&Ps[kk * LD + ty * 4];
            float4 v = *(const float4*)&Vs[kk * LD + tx * 4];
            acc[0][0] += p.x * v.x; acc[0][1] += p.x * v.y; acc[0][2] += p.x * v.z; acc[0][3] += p.x * v.w;
            acc[1][0] += p.y * v.x; acc[1][1] += p.y * v.y; acc[1][2] += p.y * v.z; acc[1][3] += p.y * v.w;
            acc[2][0] += p.z * v.x; acc[2][1] += p.z * v.y; acc[2][2] += p.z * v.z; acc[2][3] += p.z * v.w;
            acc[3][0] += p.w * v.x; acc[3][1] += p.w * v.y; acc[3][2] += p.w * v.z; acc[3][3] += p.w * v.w;
        }
    }
    __syncthreads();

    float inv[4];
#pragma unroll
    for (int i = 0; i < 4; i++) inv[i] = 1.0f / (denom[ty * 4 + i] + 1e-8f);

    // context[b, s, h*64 + d]
#pragma unroll
    for (int i = 0; i < 4; i++) {
        const int s = qt * 64 + ty * 4 + i;
        float4 o = make_float4(acc[i][0] * inv[i], acc[i][1] * inv[i],
                               acc[i][2] * inv[i], acc[i][3] * inv[i]);
        *(float4*)&ctx[(size_t)(b * S_ + s) * D_ + h * DK_ + tx * 4] = o;
    }
}

// ---------------------------------------------------------------------------
extern "C" void kernel_launch(void* const* d_in, const int* in_sizes, int n_in,
                              void* d_out, int out_size)
{
    const float* Q      = (const float*)d_in[0];
    const int*   length = (const int*)  d_in[1];
    const float* Wq     = (const float*)d_in[2];
    const float* bq     = (const float*)d_in[3];
    const float* Wk     = (const float*)d_in[4];
    const float* bk     = (const float*)d_in[5];
    const float* Wv     = (const float*)d_in[6];
    const float* bv     = (const float*)d_in[7];

    float* out = (float*)d_out;
    float* ctx = out;                                // output 0: context [B,S,D]
    float* qa  = out + (size_t)out_size / 2;         // output 1: q_a     [B,S,D]

    dim3 ggrid(24, 64);                              // (3*1024/128, 8192/128)
    qkv_gemm<<<ggrid, 256>>>(Q, Wq, bq, Wk, bk, Wv, bv, qa);

    const size_t smem = (size_t)(4 * 64 * LD + 64) * sizeof(float);  // ~70 KB
    cudaFuncSetAttribute(attn_kernel, cudaFuncAttributeMaxDynamicSharedMemorySize,
                         (int)smem);
    dim3 agrid(32, 64);                              // (S/64, B*H)
    attn_kernel<<<agrid, 256, smem>>>(length, ctx);
}

// round 14
// speedup vs baseline: 1.5099x; 1.5099x over previous
#include <cuda_runtime.h>
#include <cstdint>

#define B_  4
#define S_  2048
#define D_  1024
#define H_  16
#define DK_ 64

// Head-major scratch: [b, h, s, dk]
__device__ float g_q[B_ * H_ * S_ * DK_];
__device__ float g_k[B_ * H_ * S_ * DK_];
__device__ float g_v[B_ * H_ * S_ * DK_];

// ---------------------------------------------------------------------------
// tf32 tensor-core QKV projection: C = X @ W? + b?  (X:[8192,1024], W:[1024,1024])
// BM=BN=128, BK=32, 256 threads = 8 warps (2x4), warp tile 64x32,
// mma.sync.aligned.m16n8k8.row.col.f32.tf32.tf32.f32.
// Smem strides 36 (A) / 136 (B): both frag-load patterns bank-conflict-free.
// ---------------------------------------------------------------------------
#define GBK     32
#define ASTRIDE 36
#define BSTRIDE 136

__device__ __forceinline__ uint32_t f2tf32(float x) {
    uint32_t y;
    asm("cvt.rna.tf32.f32 %0, %1;" : "=r"(y) : "f"(x));
    return y;
}

__device__ __forceinline__ void mma_tf32(float* d, const uint32_t* a, const uint32_t* b) {
    asm volatile(
        "mma.sync.aligned.m16n8k8.row.col.f32.tf32.tf32.f32 "
        "{%0,%1,%2,%3}, {%4,%5,%6,%7}, {%8,%9}, {%0,%1,%2,%3};\n"
        : "+f"(d[0]), "+f"(d[1]), "+f"(d[2]), "+f"(d[3])
        : "r"(a[0]), "r"(a[1]), "r"(a[2]), "r"(a[3]),
          "r"(b[0]), "r"(b[1]));
}

__global__ __launch_bounds__(256) void qkv_gemm_tf32(
    const float* __restrict__ X,
    const float* __restrict__ Wq, const float* __restrict__ bq,
    const float* __restrict__ Wk, const float* __restrict__ bk,
    const float* __restrict__ Wv, const float* __restrict__ bv,
    float* __restrict__ qa_out)
{
    __shared__ uint32_t As[128 * ASTRIDE];   // [m][k] tf32 bits, 18.4 KB
    __shared__ uint32_t Bs[GBK * BSTRIDE];   // [k][n] tf32 bits, 17.4 KB

    const int nb = blockIdx.x;          // 0..23
    const int mb = blockIdx.y;          // 0..63
    const int which = nb >> 3;          // 0=q 1=k 2=v
    const int n0 = (nb & 7) * 128;
    const int m0 = mb * 128;

    const float* W;
    const float* bias;
    if (which == 0)      { W = Wq; bias = bq; }
    else if (which == 1) { W = Wk; bias = bk; }
    else                 { W = Wv; bias = bv; }

    const int tid  = threadIdx.x;
    const int lane = tid & 31;
    const int warp = tid >> 5;
    const int g    = lane >> 2;        // group id (0..7)
    const int tig  = lane & 3;         // thread in group (0..3)
    const int wm   = (warp >> 2) * 64; // warp row base in tile
    const int wn   = (warp & 3)  * 32; // warp col base in tile

    float acc[4][4][4];
#pragma unroll
    for (int mi = 0; mi < 4; mi++)
#pragma unroll
        for (int ni = 0; ni < 4; ni++)
#pragma unroll
            for (int r = 0; r < 4; r++) acc[mi][ni][r] = 0.0f;

    // gmem load indexing (per thread: 4 float4 of A, 4 float4 of B)
    // A: linear float4 id f = tid + u*256 ; row = f>>3, c4 = f&7
    // B: krow = f>>5, c4 = f&31
    float4 af[4], bf[4];
#pragma unroll
    for (int u = 0; u < 4; u++) {
        int f = tid + u * 256;
        int row = f >> 3, c4 = f & 7;
        af[u] = *(const float4*)&X[(size_t)(m0 + row) * D_ + c4 * 4];
        int krow = f >> 5, bc4 = f & 31;
        bf[u] = *(const float4*)&W[(size_t)krow * D_ + n0 + bc4 * 4];
    }

    const int NKT = D_ / GBK;  // 32
    for (int kt = 0; kt < NKT; kt++) {
        __syncthreads();  // prior tile compute done
#pragma unroll
        for (int u = 0; u < 4; u++) {
            int f = tid + u * 256;
            int row = f >> 3, c4 = f & 7;
            uint32_t* pa = &As[row * ASTRIDE + c4 * 4];
            pa[0] = f2tf32(af[u].x); pa[1] = f2tf32(af[u].y);
            pa[2] = f2tf32(af[u].z); pa[3] = f2tf32(af[u].w);
            int krow = f >> 5, bc4 = f & 31;
            uint32_t* pb = &Bs[krow * BSTRIDE + bc4 * 4];
            pb[0] = f2tf32(bf[u].x); pb[1] = f2tf32(bf[u].y);
            pb[2] = f2tf32(bf[u].z); pb[3] = f2tf32(bf[u].w);
        }
        __syncthreads();

        // prefetch next k-tile from gmem while computing this one
        if (kt + 1 < NKT) {
            const int k0 = (kt + 1) * GBK;
#pragma unroll
            for (int u = 0; u < 4; u++) {
                int f = tid + u * 256;
                int row = f >> 3, c4 = f & 7;
                af[u] = *(const float4*)&X[(size_t)(m0 + row) * D_ + k0 + c4 * 4];
                int krow = f >> 5, bc4 = f & 31;
                bf[u] = *(const float4*)&W[(size_t)(k0 + krow) * D_ + n0 + bc4 * 4];
            }
        }

#pragma unroll
        for (int ks = 0; ks < 4; ks++) {
            const int kb = ks * 8;
            uint32_t a[4][4], b[4][2];
#pragma unroll
            for (int mi = 0; mi < 4; mi++) {
                int r = wm + mi * 16 + g;
                a[mi][0] = As[r * ASTRIDE + kb + tig];
                a[mi][1] = As[(r + 8) * ASTRIDE + kb + tig];
                a[mi][2] = As[r * ASTRIDE + kb + tig + 4];
                a[mi][3] = As[(r + 8) * ASTRIDE + kb + tig + 4];
            }
#pragma unroll
            for (int ni = 0; ni < 4; ni++) {
                int c = wn + ni * 8 + g;
                b[ni][0] = Bs[(kb + tig) * BSTRIDE + c];
                b[ni][1] = Bs[(kb + tig + 4) * BSTRIDE + c];
            }
#pragma unroll
            for (int mi = 0; mi < 4; mi++)
#pragma unroll
                for (int ni = 0; ni < 4; ni++)
                    mma_tf32(acc[mi][ni], a[mi], b[ni]);
        }
    }

    // Epilogue: bias + route. c/d frag layout: (row g, col 2*tig), (g, 2*tig+1),
    // (g+8, 2*tig), (g+8, 2*tig+1).
#pragma unroll
    for (int mi = 0; mi < 4; mi++) {
#pragma unroll
        for (int ni = 0; ni < 4; ni++) {
            const int c = n0 + wn + ni * 8 + tig * 2;      // column (even)
            const float bx = bias[c], by = bias[c + 1];
            const int h  = c >> 6;
            const int dk = c & 63;
#pragma unroll
            for (int half = 0; half < 2; half++) {
                const int r = m0 + wm + mi * 16 + g + half * 8;
                const float vx = acc[mi][ni][half * 2 + 0] + bx;
                const float vy = acc[mi][ni][half * 2 + 1] + by;
                const int b = r >> 11;
                const int s = r & 2047;
                const size_t hidx = (size_t)((b * H_ + h) * S_ + s) * DK_ + dk;
                const float2 v2 = make_float2(vx, vy);
                if (which == 0) {
                    *(float2*)&qa_out[(size_t)r * D_ + c] = v2;
                    *(float2*)&g_q[hidx] = v2;
                } else if (which == 1) {
                    *(float2*)&g_k[hidx] = v2;
                } else {
                    *(float2*)&g_v[hidx] = v2;
                }
            }
        }
    }
}

// ---------------------------------------------------------------------------
// Flash-style attention per (b,h) and 64-query tile (unchanged from R13 pass).
// ---------------------------------------------------------------------------
#define LD 68

__global__ __launch_bounds__(256) void attn_kernel(
    const int* __restrict__ length, float* __restrict__ ctx)
{
    extern __shared__ float sm[];
    float* Qs    = sm;               // [d][q]
    float* Ks    = sm + 64 * LD;     // [d][k]
    float* Vs    = sm + 2 * 64 * LD; // [k][d]
    float* Ps    = sm + 3 * 64 * LD; // [k][q]
    float* denom = sm + 4 * 64 * LD; // [64]

    const int bh = blockIdx.y;
    const int b  = bh >> 4;
    const int qt = blockIdx.x;
    const int len = length[b];

    const int tid = threadIdx.x;
    const int tx  = tid & 15;
    const int ty  = tid >> 4;

    const float* qbase = g_q + (size_t)(bh * S_ + qt * 64) * DK_;
#pragma unroll
    for (int it = 0; it < 16; it++) {
        int lin = it * 256 + tid;
        int s = lin >> 6, d = lin & 63;
        Qs[d * LD + s] = qbase[lin];
    }
    if (tid < 64) denom[tid] = 0.0f;

    float acc[4][4];
#pragma unroll
    for (int i = 0; i < 4; i++)
#pragma unroll
        for (int j = 0; j < 4; j++) acc[i][j] = 0.0f;

    const int nkt = (len + 63) >> 6;
    for (int kt = 0; kt < nkt; kt++) {
        __syncthreads();
        const float* kb = g_k + (size_t)(bh * S_ + kt * 64) * DK_;
        const float* vb = g_v + (size_t)(bh * S_ + kt * 64) * DK_;
#pragma unroll
        for (int it = 0; it < 16; it++) {
            int lin = it * 256 + tid;
            int r = lin >> 6, d = lin & 63;
            Ks[d * LD + r] = kb[lin];
            Vs[r * LD + d] = vb[lin];
        }
        __syncthreads();

        float sc[4][4];
#pragma unroll
        for (int i = 0; i < 4; i++)
#pragma unroll
            for (int j = 0; j < 4; j++) sc[i][j] = 0.0f;

#pragma unroll 16
        for (int d = 0; d < 64; d++) {
            float4 a  = *(const float4*)&Qs[d * LD + ty * 4];
            float4 kk = *(const float4*)&Ks[d * LD + tx * 4];
            sc[0][0] += a.x * kk.x; sc[0][1] += a.x * kk.y; sc[0][2] += a.x * kk.z; sc[0][3] += a.x * kk.w;
            sc[1][0] += a.y * kk.x; sc[1][1] += a.y * kk.y; sc[1][2] += a.y * kk.z; sc[1][3] += a.y * kk.w;
            sc[2][0] += a.z * kk.x; sc[2][1] += a.z * kk.y; sc[2][2] += a.z * kk.z; sc[2][3] += a.z * kk.w;
            sc[3][0] += a.w * kk.x; sc[3][1] += a.w * kk.y; sc[3][2] += a.w * kk.z; sc[3][3] += a.w * kk.w;
        }

        float rs[4] = {0.0f, 0.0f, 0.0f, 0.0f};
        const int kg0 = kt * 64 + tx * 4;
#pragma unroll
        for (int j = 0; j < 4; j++) {
            const float m = (kg0 + j < len) ? 1.0f : 0.0f;
#pragma unroll
            for (int i = 0; i < 4; i++) {
                float e = __expf(sc[i][j] * 0.125f) * m;
                Ps[(tx * 4 + j) * LD + ty * 4 + i] = e;
                rs[i] += e;
            }
        }
#pragma unroll
        for (int off = 1; off < 16; off <<= 1) {
#pragma unroll
            for (int i = 0; i < 4; i++)
                rs[i] += __shfl_xor_sync(0xffffffffu, rs[i], off);
        }
        if (tx == 0) {
#pragma unroll
            for (int i = 0; i < 4; i++) denom[ty * 4 + i] += rs[i];
        }
        __syncthreads();

#pragma unroll 16
        for (int kk = 0; kk < 64; kk++) {
            float4 p = *(const float4*)&Ps[kk * LD + ty * 4];
            float4 v = *(const float4*)&Vs[kk * LD + tx * 4];
            acc[0][0] += p.x * v.x; acc[0][1] += p.x * v.y; acc[0][2] += p.x * v.z; acc[0][3] += p.x * v.w;
            acc[1][0] += p.y * v.x; acc[1][1] += p.y * v.y; acc[1][2] += p.y * v.z; acc[1][3] += p.y * v.w;
            acc[2][0] += p.z * v.x; acc[2][1] += p.z * v.y; acc[2][2] += p.z * v.z; acc[2][3] += p.z * v.w;
            acc[3][0] += p.w * v.x; acc[3][1] += p.w * v.y; acc[3][2] += p.w * v.z; acc[3][3] += p.w * v.w;
        }
    }
    __syncthreads();

    float inv[4];
#pragma unroll
    for (int i = 0; i < 4; i++) inv[i] = 1.0f / (denom[ty * 4 + i] + 1e-8f);

    const int h = bh & 15;
#pragma unroll
    for (int i = 0; i < 4; i++) {
        const int s = qt * 64 + ty * 4 + i;
        float4 o = make_float4(acc[i][0] * inv[i], acc[i][1] * inv[i],
                               acc[i][2] * inv[i], acc[i][3] * inv[i]);
        *(float4*)&ctx[(size_t)(b * S_ + s) * D_ + h * DK_ + tx * 4] = o;
    }
}

// ---------------------------------------------------------------------------
extern "C" void kernel_launch(void* const* d_in, const int* in_sizes, int n_in,
                              void* d_out, int out_size)
{
    const float* Q      = (const float*)d_in[0];
    const int*   length = (const int*)  d_in[1];
    const float* Wq     = (const float*)d_in[2];
    const float* bq     = (const float*)d_in[3];
    const float* Wk     = (const float*)d_in[4];
    const float* bk     = (const float*)d_in[5];
    const float* Wv     = (const float*)d_in[6];
    const float* bv     = (const float*)d_in[7];

    float* out = (float*)d_out;
    float* ctx = out;
    float* qa  = out + (size_t)out_size / 2;

    dim3 ggrid(24, 64);
    qkv_gemm_tf32<<<ggrid, 256>>>(Q, Wq, bq, Wk, bk, Wv, bv, qa);

    const size_t smem = (size_t)(4 * 64 * LD + 64) * sizeof(float);
    cudaFuncSetAttribute(attn_kernel, cudaFuncAttributeMaxDynamicSharedMemorySize,
                         (int)smem);
    dim3 agrid(32, 64);
    attn_kernel<<<agrid, 256, smem>>>(length, ctx);
}

// round 15
// speedup vs baseline: 1.5125x; 1.0017x over previous
#include <cuda_runtime.h>
#include <cstdint>

#define B_  4
#define S_  2048
#define D_  1024
#define H_  16
#define DK_ 64

// Head-major scratch: [b, h, s, dk]
__device__ float g_q[B_ * H_ * S_ * DK_];
__device__ float g_k[B_ * H_ * S_ * DK_];
__device__ float g_v[B_ * H_ * S_ * DK_];

// ---------------------------------------------------------------------------
// tf32 tensor-core QKV projection: C = X @ W? + b?  (X:[8192,1024], W:[1024,1024])
// BM=BN=128, BK=32, 256 threads = 8 warps (2x4), warp tile 64x32,
// mma.sync.aligned.m16n8k8.row.col.f32.tf32.tf32.f32.
// Smem strides 36 (A) / 136 (B): both frag-load patterns bank-conflict-free.
// ---------------------------------------------------------------------------
#define GBK     32
#define ASTRIDE 36
#define BSTRIDE 136

__device__ __forceinline__ uint32_t f2tf32(float x) {
    uint32_t y;
    asm("cvt.rna.tf32.f32 %0, %1;" : "=r"(y) : "f"(x));
    return y;
}

__device__ __forceinline__ void mma_tf32(float* d, const uint32_t* a, const uint32_t* b) {
    asm volatile(
        "mma.sync.aligned.m16n8k8.row.col.f32.tf32.tf32.f32 "
        "{%0,%1,%2,%3}, {%4,%5,%6,%7}, {%8,%9}, {%0,%1,%2,%3};\n"
        : "+f"(d[0]), "+f"(d[1]), "+f"(d[2]), "+f"(d[3])
        : "r"(a[0]), "r"(a[1]), "r"(a[2]), "r"(a[3]),
          "r"(b[0]), "r"(b[1]));
}

__global__ __launch_bounds__(256) void qkv_gemm_tf32(
    const float* __restrict__ X,
    const float* __restrict__ Wq, const float* __restrict__ bq,
    const float* __restrict__ Wk, const float* __restrict__ bk,
    const float* __restrict__ Wv, const float* __restrict__ bv,
    float* __restrict__ qa_out)
{
    __shared__ uint32_t As[128 * ASTRIDE];   // [m][k] tf32 bits, 18.4 KB
    __shared__ uint32_t Bs[GBK * BSTRIDE];   // [k][n] tf32 bits, 17.4 KB

    const int nb = blockIdx.x;          // 0..23
    const int mb = blockIdx.y;          // 0..63
    const int which = nb >> 3;          // 0=q 1=k 2=v
    const int n0 = (nb & 7) * 128;
    const int m0 = mb * 128;

    const float* W;
    const float* bias;
    if (which == 0)      { W = Wq; bias = bq; }
    else if (which == 1) { W = Wk; bias = bk; }
    else                 { W = Wv; bias = bv; }

    const int tid  = threadIdx.x;
    const int lane = tid & 31;
    const int warp = tid >> 5;
    const int g    = lane >> 2;        // group id (0..7)
    const int tig  = lane & 3;         // thread in group (0..3)
    const int wm   = (warp >> 2) * 64; // warp row base in tile
    const int wn   = (warp & 3)  * 32; // warp col base in tile

    float acc[4][4][4];
#pragma unroll
    for (int mi = 0; mi < 4; mi++)
#pragma unroll
        for (int ni = 0; ni < 4; ni++)
#pragma unroll
            for (int r = 0; r < 4; r++) acc[mi][ni][r] = 0.0f;

    // gmem load indexing (per thread: 4 float4 of A, 4 float4 of B)
    // A: linear float4 id f = tid + u*256 ; row = f>>3, c4 = f&7
    // B: krow = f>>5, c4 = f&31
    float4 af[4], bf[4];
#pragma unroll
    for (int u = 0; u < 4; u++) {
        int f = tid + u * 256;
        int row = f >> 3, c4 = f & 7;
        af[u] = *(const float4*)&X[(size_t)(m0 + row) * D_ + c4 * 4];
        int krow = f >> 5, bc4 = f & 31;
        bf[u] = *(const float4*)&W[(size_t)krow * D_ + n0 + bc4 * 4];
    }

    const int NKT = D_ / GBK;  // 32
    for (int kt = 0; kt < NKT; kt++) {
        __syncthreads();  // prior tile compute done
#pragma unroll
        for (int u = 0; u < 4; u++) {
            int f = tid + u * 256;
            int row = f >> 3, c4 = f & 7;
            uint32_t* pa = &As[row * ASTRIDE + c4 * 4];
            pa[0] = f2tf32(af[u].x); pa[1] = f2tf32(af[u].y);
            pa[2] = f2tf32(af[u].z); pa[3] = f2tf32(af[u].w);
            int krow = f >> 5, bc4 = f & 31;
            uint32_t* pb = &Bs[krow * BSTRIDE + bc4 * 4];
            pb[0] = f2tf32(bf[u].x); pb[1] = f2tf32(bf[u].y);
            pb[2] = f2tf32(bf[u].z); pb[3] = f2tf32(bf[u].w);
        }
        __syncthreads();

        // prefetch next k-tile from gmem while computing this one
        if (kt + 1 < NKT) {
            const int k0 = (kt + 1) * GBK;
#pragma unroll
            for (int u = 0; u < 4; u++) {
                int f = tid + u * 256;
                int row = f >> 3, c4 = f & 7;
                af[u] = *(const float4*)&X[(size_t)(m0 + row) * D_ + k0 + c4 * 4];
                int krow = f >> 5, bc4 = f & 31;
                bf[u] = *(const float4*)&W[(size_t)(k0 + krow) * D_ + n0 + bc4 * 4];
            }
        }

#pragma unroll
        for (int ks = 0; ks < 4; ks++) {
            const int kb = ks * 8;
            uint32_t a[4][4], b[4][2];
#pragma unroll
            for (int mi = 0; mi < 4; mi++) {
                int r = wm + mi * 16 + g;
                a[mi][0] = As[r * ASTRIDE + kb + tig];
                a[mi][1] = As[(r + 8) * ASTRIDE + kb + tig];
                a[mi][2] = As[r * ASTRIDE + kb + tig + 4];
                a[mi][3] = As[(r + 8) * ASTRIDE + kb + tig + 4];
            }
#pragma unroll
            for (int ni = 0; ni < 4; ni++) {
                int c = wn + ni * 8 + g;
                b[ni][0] = Bs[(kb + tig) * BSTRIDE + c];
                b[ni][1] = Bs[(kb + tig + 4) * BSTRIDE + c];
            }
#pragma unroll
            for (int mi = 0; mi < 4; mi++)
#pragma unroll
                for (int ni = 0; ni < 4; ni++)
                    mma_tf32(acc[mi][ni], a[mi], b[ni]);
        }
    }

    // Epilogue: bias + route. c/d frag layout: (row g, col 2*tig), (g, 2*tig+1),
    // (g+8, 2*tig), (g+8, 2*tig+1).
#pragma unroll
    for (int mi = 0; mi < 4; mi++) {
#pragma unroll
        for (int ni = 0; ni < 4; ni++) {
            const int c = n0 + wn + ni * 8 + tig * 2;      // column (even)
            const float bx = bias[c], by = bias[c + 1];
            const int h  = c >> 6;
            const int dk = c & 63;
#pragma unroll
            for (int half = 0; half < 2; half++) {
                const int r = m0 + wm + mi * 16 + g + half * 8;
                const float vx = acc[mi][ni][half * 2 + 0] + bx;
                const float vy = acc[mi][ni][half * 2 + 1] + by;
                const int b = r >> 11;
                const int s = r & 2047;
                const size_t hidx = (size_t)((b * H_ + h) * S_ + s) * DK_ + dk;
                const float2 v2 = make_float2(vx, vy);
                if (which == 0) {
                    *(float2*)&qa_out[(size_t)r * D_ + c] = v2;
                    *(float2*)&g_q[hidx] = v2;
                } else if (which == 1) {
                    *(float2*)&g_k[hidx] = v2;
                } else {
                    *(float2*)&g_v[hidx] = v2;
                }
            }
        }
    }
}

// ---------------------------------------------------------------------------
// Flash-style attention per (b,h) and 64-query tile (unchanged from R13 pass).
// ---------------------------------------------------------------------------
#define LD 68

__global__ __launch_bounds__(256) void attn_kernel(
    const int* __restrict__ length, float* __restrict__ ctx)
{
    extern __shared__ float sm[];
    float* Qs    = sm;               // [d][q]
    float* Ks    = sm + 64 * LD;     // [d][k]
    float* Vs    = sm + 2 * 64 * LD; // [k][d]
    float* Ps    = sm + 3 * 64 * LD; // [k][q]
    float* denom = sm + 4 * 64 * LD; // [64]

    const int bh = blockIdx.y;
    const int b  = bh >> 4;
    const int qt = blockIdx.x;
    const int len = length[b];

    const int tid = threadIdx.x;
    const int tx  = tid & 15;
    const int ty  = tid >> 4;

    const float* qbase = g_q + (size_t)(bh * S_ + qt * 64) * DK_;
#pragma unroll
    for (int it = 0; it < 16; it++) {
        int lin = it * 256 + tid;
        int s = lin >> 6, d = lin & 63;
        Qs[d * LD + s] = qbase[lin];
    }
    if (tid < 64) denom[tid] = 0.0f;

    float acc[4][4];
#pragma unroll
    for (int i = 0; i < 4; i++)
#pragma unroll
        for (int j = 0; j < 4; j++) acc[i][j] = 0.0f;

    const int nkt = (len + 63) >> 6;
    for (int kt = 0; kt < nkt; kt++) {
        __syncthreads();
        const float* kb = g_k + (size_t)(bh * S_ + kt * 64) * DK_;
        const float* vb = g_v + (size_t)(bh * S_ + kt * 64) * DK_;
#pragma unroll
        for (int it = 0; it < 16; it++) {
            int lin = it * 256 + tid;
            int r = lin >> 6, d = lin & 63;
            Ks[d * LD + r] = kb[lin];
            Vs[r * LD + d] = vb[lin];
        }
        __syncthreads();

        float sc[4][4];
#pragma unroll
        for (int i = 0; i < 4; i++)
#pragma unroll
            for (int j = 0; j < 4; j++) sc[i][j] = 0.0f;

#pragma unroll 16
        for (int d = 0; d < 64; d++) {
            float4 a  = *(const float4*)&Qs[d * LD + ty * 4];
            float4 kk = *(const float4*)&Ks[d * LD + tx * 4];
            sc[0][0] += a.x * kk.x; sc[0][1] += a.x * kk.y; sc[0][2] += a.x * kk.z; sc[0][3] += a.x * kk.w;
            sc[1][0] += a.y * kk.x; sc[1][1] += a.y * kk.y; sc[1][2] += a.y * kk.z; sc[1][3] += a.y * kk.w;
            sc[2][0] += a.z * kk.x; sc[2][1] += a.z * kk.y; sc[2][2] += a.z * kk.z; sc[2][3] += a.z * kk.w;
            sc[3][0] += a.w * kk.x; sc[3][1] += a.w * kk.y; sc[3][2] += a.w * kk.z; sc[3][3] += a.w * kk.w;
        }

        float rs[4] = {0.0f, 0.0f, 0.0f, 0.0f};
        const int kg0 = kt * 64 + tx * 4;
#pragma unroll
        for (int j = 0; j < 4; j++) {
            const float m = (kg0 + j < len) ? 1.0f : 0.0f;
#pragma unroll
            for (int i = 0; i < 4; i++) {
                float e = __expf(sc[i][j] * 0.125f) * m;
                Ps[(tx * 4 + j) * LD + ty * 4 + i] = e;
                rs[i] += e;
            }
        }
#pragma unroll
        for (int off = 1; off < 16; off <<= 1) {
#pragma unroll
            for (int i = 0; i < 4; i++)
                rs[i] += __shfl_xor_sync(0xffffffffu, rs[i], off);
        }
        if (tx == 0) {
#pragma unroll
            for (int i = 0; i < 4; i++) denom[ty * 4 + i] += rs[i];
        }
        __syncthreads();

#pragma unroll 16
        for (int kk = 0; kk < 64; kk++) {
            float4 p = *(const float4*)&Ps[kk * LD + ty * 4];
            float4 v = *(const float4*)&Vs[kk * LD + tx * 4];
            acc[0][0] += p.x * v.x; acc[0][1] += p.x * v.y; acc[0][2] += p.x * v.z; acc[0][3] += p.x * v.w;
            acc[1][0] += p.y * v.x; acc[1][1] += p.y * v.y; acc[1][2] += p.y * v.z; acc[1][3] += p.y * v.w;
            acc[2][0] += p.z * v.x; acc[2][1] += p.z * v.y; acc[2][2] += p.z * v.z; acc[2][3] += p.z * v.w;
            acc[3][0] += p.w * v.x; acc[3][1] += p.w * v.y; acc[3][2] += p.w * v.z; acc[3][3] += p.w * v.w;
        }
    }
    __syncthreads();

    float inv[4];
#pragma unroll
    for (int i = 0; i < 4; i++) inv[i] = 1.0f / (denom[ty * 4 + i] + 1e-8f);

    const int h = bh & 15;
#pragma unroll
    for (int i = 0; i < 4; i++) {
        const int s = qt * 64 + ty * 4 + i;
        float4 o = make_float4(acc[i][0] * inv[i], acc[i][1] * inv[i],
                               acc[i][2] * inv[i], acc[i][3] * inv[i]);
        *(float4*)&ctx[(size_t)(b * S_ + s) * D_ + h * DK_ + tx * 4] = o;
    }
}

// ---------------------------------------------------------------------------
extern "C" void kernel_launch(void* const* d_in, const int* in_sizes, int n_in,
                              void* d_out, int out_size)
{
    const float* Q      = (const float*)d_in[0];
    const int*   length = (const int*)  d_in[1];
    const float* Wq     = (const float*)d_in[2];
    const float* bq     = (const float*)d_in[3];
    const float* Wk     = (const float*)d_in[4];
    const float* bk     = (const float*)d_in[5];
    const float* Wv     = (const float*)d_in[6];
    const float* bv     = (const float*)d_in[7];

    float* out = (float*)d_out;
    float* ctx = out;
    float* qa  = out + (size_t)out_size / 2;

    dim3 ggrid(24, 64);
    qkv_gemm_tf32<<<ggrid, 256>>>(Q, Wq, bq, Wk, bk, Wv, bv, qa);

    const size_t smem = (size_t)(4 * 64 * LD + 64) * sizeof(float);
    cudaFuncSetAttribute(attn_kernel, cudaFuncAttributeMaxDynamicSharedMemorySize,
                         (int)smem);
    dim3 agrid(32, 64);
    attn_kernel<<<agrid, 256, smem>>>(length, ctx);
}